// round 2
// baseline (speedup 1.0000x reference)
#include <cuda_runtime.h>
#include <cuda_bf16.h>

// Problem constants
#define BSZ 32
#define TT  200
#define RR  512
#define FF  128
#define BR  4
#define CC  10
#define K2  1024          // 2*R
#define NNZ 256           // nonzeros per branch row (K2/BR)
#define NROWS 2048        // R*BR
#define VTH 0.5f

#define NCTA 128          // persistent grid for recurrent kernel
// per CTA: 16 neurons (64 rows) x 8 batches
#define NG_NEUR 16
#define NG_ROWS 64
#define NG_BAT  8

#define OUT0 (BSZ*CC*TT)  // offset of spikes block in d_out (64000)

// -------- scratch (device globals; no allocation allowed) --------
__device__ float          g_currents[TT * BSZ * RR];       // [T][B][R]
__device__ float          g_spk[2][BSZ * RR];              // ping-pong spike state
__device__ unsigned short g_idx[NROWS * NNZ];              // compacted mask indices
__device__ float          g_wv [NROWS * NNZ];              // compacted masked weights
__device__ unsigned       g_bar_count;
__device__ unsigned       g_bar_sense;

__device__ __forceinline__ float sigmoidf_(float x) { return 1.f / (1.f + __expf(-x)); }

// -------- init: reset all cross-launch state (graph replays reuse globals) ----
__global__ void k_init() {
    int tid = blockIdx.x * blockDim.x + threadIdx.x;
    int n = 2 * BSZ * RR;
    for (int i = tid; i < n; i += gridDim.x * blockDim.x) ((float*)g_spk)[i] = 0.f;
    if (tid == 0) { g_bar_count = 0; g_bar_sense = 0; }
}

// -------- kernel A: currents[t][b][r] = dot(input[b][t][r][:], w_in) + b_in --
__global__ void k_currents(const float* __restrict__ inp,
                           const float* __restrict__ w_in,
                           const float* __restrict__ b_in) {
    __shared__ float sw[FF];
    int tid = threadIdx.x;
    if (tid < FF) sw[tid] = w_in[tid];
    __syncthreads();
    int lane = tid & 31, wid = tid >> 5;
    long long rid = (long long)blockIdx.x * 8 + wid;   // row over (b,t,r)
    if (rid >= (long long)BSZ * TT * RR) return;
    const float4* p = (const float4*)inp + rid * (FF / 4);
    float4 v = p[lane];
    float4 w = ((const float4*)sw)[lane];
    float s = v.x * w.x + v.y * w.y + v.z * w.z + v.w * w.w;
    #pragma unroll
    for (int o = 16; o; o >>= 1) s += __shfl_xor_sync(0xffffffffu, s, o);
    if (lane == 0) {
        int r = (int)(rid % RR);
        long long bt = rid / RR;
        int t = (int)(bt % TT);
        int b = (int)(bt / TT);
        g_currents[((long long)t * BSZ + b) * RR + r] = s + b_in[0];
    }
}

// -------- prep: compact (w_rnn*mask) rows into 256 (idx, w) pairs -----------
__global__ void k_prep(const float* __restrict__ w_rnn,
                       const float* __restrict__ mask) {
    int row = blockIdx.x * 8 + (threadIdx.x >> 5);
    int lane = threadIdx.x & 31;
    if (row >= NROWS) return;
    int base = 0;
    for (int c0 = 0; c0 < K2; c0 += 32) {
        float m = mask[(long long)row * K2 + c0 + lane];
        unsigned bal = __ballot_sync(0xffffffffu, m != 0.f);
        int pre = __popc(bal & ((1u << lane) - 1u));
        if (m != 0.f) {
            int pos = base + pre;
            if (pos < NNZ) {
                g_idx[row * NNZ + pos] = (unsigned short)(c0 + lane);
                g_wv [row * NNZ + pos] = w_rnn[(long long)row * K2 + c0 + lane];
            }
        }
        base += __popc(bal);
    }
}

// -------- kernel B: persistent recurrent scan -------------------------------
__global__ void __launch_bounds__(256, 1)
k_recurrent(const float* __restrict__ gating,
            const float* __restrict__ b_rnn,
            const float* __restrict__ tau_m,
            const float* __restrict__ tau_n,
            const float* __restrict__ w_ro,
            const float* __restrict__ b_ro,
            const float* __restrict__ tau_m_ro,
            float* __restrict__ out) {
    extern __shared__ char sm[];
    float*          s_w    = (float*)sm;                       // 64*256 f32
    unsigned short* s_idx  = (unsigned short*)(s_w + NG_ROWS * NNZ);   // 64*256 u16
    float*          s_kT   = (float*)(s_idx + NG_ROWS * NNZ);  // 1024*8 f32 (16B aligned)
    float*          s_proj = s_kT + K2 * NG_BAT;               // 8*64
    float*          s_d    = s_proj + NG_BAT * NG_ROWS;        // 8*16*4
    float*          s_mem  = s_d + NG_BAT * NG_NEUR * BR;      // 8*16
    float*          s_spk  = s_mem + NG_BAT * NG_NEUR;         // 8*16
    float*          s_beta = s_spk + NG_BAT * NG_NEUR;         // 64
    float*          s_alpha= s_beta + NG_ROWS;                 // 16
    float*          s_brnn = s_alpha + NG_NEUR;                // 64
    float*          s_memo = s_brnn + NG_ROWS;                 // 10
    float*          s_spko = s_memo + CC;                      // 10
    float*          s_ao   = s_spko + CC;                      // 10
    float*          s_bro  = s_ao + CC;                        // 10

    int tid = threadIdx.x, lane = tid & 31, wid = tid >> 5;
    int bid = blockIdx.x;
    int ng = bid >> 2;            // 0..31 neuron group (16 neurons)
    int bg = bid & 3;             // 0..3  batch group (8 batches)
    int row0 = ng * NG_ROWS;      // global branch-row base
    int b0 = bg * NG_BAT;

    // load resident weights/indices
    for (int i = tid; i < NG_ROWS * NNZ; i += 256) {
        s_w[i]   = g_wv [row0 * NNZ + i];
        s_idx[i] = g_idx[row0 * NNZ + i];
    }
    if (tid < NG_ROWS) {
        s_beta[tid] = sigmoidf_(tau_n[(ng * NG_NEUR + (tid >> 2)) * BR + (tid & 3)]);
        s_brnn[tid] = b_rnn[row0 + tid];
    }
    if (tid < NG_NEUR) s_alpha[tid] = sigmoidf_(tau_m[ng * NG_NEUR + tid]);
    for (int i = tid; i < NG_BAT * NG_NEUR * BR; i += 256) s_d[i] = 0.f;
    if (tid < NG_BAT * NG_NEUR) { s_mem[tid] = 0.f; s_spk[tid] = 0.f; }
    if (bid < BSZ && tid < CC) {
        s_memo[tid] = 0.f; s_spko[tid] = 0.f;
        s_ao[tid] = sigmoidf_(tau_m_ro[tid]); s_bro[tid] = b_ro[tid];
    }
    __syncthreads();

    for (int t = 0; t < TT; t++) {
        // ---- phase 1: fill kT = [currents(t) ; spk(prev)] transposed -------
        const float* cur = g_currents + (long long)t * BSZ * RR;
        const float* sp  = g_spk[t & 1];
        for (int e = tid; e < NG_BAT * RR; e += 256) {
            int bl = e >> 9, r = e & (RR - 1);
            s_kT[r * NG_BAT + bl]        = cur[(b0 + bl) * RR + r];
            s_kT[(RR + r) * NG_BAT + bl] = sp [(b0 + bl) * RR + r];
        }
        __syncthreads();

        // ---- phase 2: sparse GEMM, warp = one branch row at a time ---------
        #pragma unroll 1
        for (int rr = 0; rr < 8; rr++) {
            int row = wid * 8 + rr;
            const float*          wp = s_w   + row * NNZ;
            const unsigned short* ip = s_idx + row * NNZ;
            float a0=0,a1=0,a2=0,a3=0,a4=0,a5=0,a6=0,a7=0;
            #pragma unroll
            for (int c = 0; c < 8; c++) {
                int j = c * 32 + lane;
                float wv = wp[j];
                int id = ip[j];
                const float4* kp = (const float4*)(s_kT + id * NG_BAT);
                float4 q0 = kp[0], q1 = kp[1];
                a0 = fmaf(wv, q0.x, a0); a1 = fmaf(wv, q0.y, a1);
                a2 = fmaf(wv, q0.z, a2); a3 = fmaf(wv, q0.w, a3);
                a4 = fmaf(wv, q1.x, a4); a5 = fmaf(wv, q1.y, a5);
                a6 = fmaf(wv, q1.z, a6); a7 = fmaf(wv, q1.w, a7);
            }
            #pragma unroll
            for (int o = 16; o; o >>= 1) {
                a0 += __shfl_xor_sync(0xffffffffu, a0, o);
                a1 += __shfl_xor_sync(0xffffffffu, a1, o);
                a2 += __shfl_xor_sync(0xffffffffu, a2, o);
                a3 += __shfl_xor_sync(0xffffffffu, a3, o);
                a4 += __shfl_xor_sync(0xffffffffu, a4, o);
                a5 += __shfl_xor_sync(0xffffffffu, a5, o);
                a6 += __shfl_xor_sync(0xffffffffu, a6, o);
                a7 += __shfl_xor_sync(0xffffffffu, a7, o);
            }
            if (lane < 8) {
                float tot = lane==0?a0: lane==1?a1: lane==2?a2: lane==3?a3:
                            lane==4?a4: lane==5?a5: lane==6?a6: a7;
                s_proj[lane * NG_ROWS + row] = tot;
            }
        }
        __syncthreads();

        // ---- phase 3: dendrite + soma + gating + spike write ---------------
        if (tid < NG_BAT * NG_NEUR) {
            int bl = tid >> 4, nl = tid & 15;
            int b = b0 + bl, r = ng * NG_NEUR + nl;
            float g = gating[((long long)b * TT + t) * RR + r];
            float lin = 0.f;
            #pragma unroll
            for (int br = 0; br < BR; br++) {
                int row = nl * BR + br;
                float proj = s_proj[bl * NG_ROWS + row] + s_brnn[row];
                float beta = s_beta[row];
                float dold = s_d[(bl * NG_NEUR + nl) * BR + br];
                float dnew = beta * dold + (1.f - beta) * proj;
                lin += dnew;
                s_d[(bl * NG_NEUR + nl) * BR + br] = g * dnew + (1.f - g) * dold;
            }
            float alpha = s_alpha[nl];
            float mold = s_mem[bl * NG_NEUR + nl];
            float sold = s_spk[bl * NG_NEUR + nl];
            float mnew = mold * alpha + (1.f - alpha) * lin - VTH * sold;
            float snew = (mnew - VTH) > 0.f ? 1.f : 0.f;
            float mg = g * mnew + (1.f - g) * mold;
            float sg = g * snew + (1.f - g) * sold;
            s_mem[bl * NG_NEUR + nl] = mg;
            s_spk[bl * NG_NEUR + nl] = sg;
            g_spk[(t + 1) & 1][b * RR + r] = sg;
            out[OUT0 + ((long long)b * RR + r) * TT + t] = sg;
        }
        __syncthreads();

        // ---- global barrier (sense-reversing; one per step) ----------------
        if (tid == 0) {
            __threadfence();
            if (atomicAdd(&g_bar_count, 1u) == NCTA - 1) {
                atomicExch(&g_bar_count, 0u);
                __threadfence();
                atomicExch(&g_bar_sense, (unsigned)(t + 1));
            } else {
                while (*(volatile unsigned*)&g_bar_sense < (unsigned)(t + 1)) {
                    __nanosleep(32);
                }
            }
            __threadfence();
        }
        __syncthreads();

        // ---- readout LIF: CTA b (bid<32) handles batch b -------------------
        if (bid < BSZ) {
            const float* spn = g_spk[(t + 1) & 1] + bid * RR;
            for (int c = wid; c < CC; c += 8) {
                float s = 0.f;
                for (int i = lane; i < RR; i += 32)
                    s += spn[i] * __ldg(&w_ro[c * RR + i]);
                #pragma unroll
                for (int o = 16; o; o >>= 1) s += __shfl_xor_sync(0xffffffffu, s, o);
                if (lane == 0) {
                    float ro = s + s_bro[c];
                    float ao = s_ao[c];
                    float mo = s_memo[c] * ao + (1.f - ao) * ro - VTH * s_spko[c];
                    float so = (mo - VTH) > 0.f ? 1.f : 0.f;
                    s_memo[c] = mo; s_spko[c] = so;
                    out[((long long)bid * CC + c) * TT + t] = mo;
                }
            }
        }
        // no extra barrier needed: readout reads buffer not written until t+1's
        // phase 3, and this CTA's own phase 3 writes come after its next barrier.
    }
}

extern "C" void kernel_launch(void* const* d_in, const int* in_sizes, int n_in,
                              void* d_out, int out_size) {
    const float* inp      = (const float*)d_in[0];
    const float* gating   = (const float*)d_in[1];
    const float* w_in     = (const float*)d_in[2];
    const float* b_in     = (const float*)d_in[3];
    const float* w_rnn    = (const float*)d_in[4];
    const float* b_rnn    = (const float*)d_in[5];
    const float* tau_m    = (const float*)d_in[6];
    const float* tau_n    = (const float*)d_in[7];
    const float* w_ro     = (const float*)d_in[8];
    const float* b_ro     = (const float*)d_in[9];
    const float* tau_m_ro = (const float*)d_in[10];
    const float* mask     = (const float*)d_in[11];
    float* out = (float*)d_out;

    // dynamic smem for recurrent kernel
    // 65536(w) + 32768(idx) + 32768(kT) + 2048(proj) + 2048(d) + 512 + 512
    // + 256(beta) + 64(alpha) + 256(brnn) + 4*40(readout) = 136928 -> pad
    static int smem_set = 0;
    int smem_bytes = 137216;
    if (!smem_set) {
        cudaFuncSetAttribute(k_recurrent,
                             cudaFuncAttributeMaxDynamicSharedMemorySize,
                             smem_bytes);
        smem_set = 1;
    }

    k_init<<<64, 256>>>();

    long long total_rows = (long long)BSZ * TT * RR;   // 3,276,800
    int gridA = (int)((total_rows + 7) / 8);
    k_currents<<<gridA, 256>>>(inp, w_in, b_in);

    k_prep<<<NROWS / 8, 256>>>(w_rnn, mask);

    k_recurrent<<<NCTA, 256, smem_bytes>>>(gating, b_rnn, tau_m, tau_n,
                                           w_ro, b_ro, tau_m_ro, out);
}

// round 3
// speedup vs baseline: 1.0045x; 1.0045x over previous
#include <cuda_runtime.h>
#include <cuda_bf16.h>

// Problem constants
#define BSZ 32
#define TT  200
#define RR  512
#define FF  128
#define BR  4
#define CC  10
#define K2  1024          // 2*R
#define NNZ 256           // nonzeros per branch row (K2/BR)
#define NROWS 2048        // R*BR
#define VTH 0.5f

#define NCTA 128          // persistent grid for recurrent kernel
// per CTA: 16 neurons (64 rows) x 8 batches
#define NG_NEUR 16
#define NG_ROWS 64
#define NG_BAT  8

#define OUT0 (BSZ*CC*TT)  // offset of spikes block in d_out (64000)

// -------- scratch (device globals; no allocation allowed) --------
__device__ float          g_currents[TT * BSZ * RR];       // [T][B][R]
__device__ float          g_spk[2][BSZ * RR];              // ping-pong spike state
__device__ unsigned short g_idx[NROWS * NNZ];              // compacted mask indices
__device__ float          g_wv [NROWS * NNZ];              // compacted masked weights
__device__ unsigned       g_bar_count;
__device__ unsigned       g_bar_sense;

__device__ __forceinline__ float sigmoidf_(float x) { return 1.f / (1.f + __expf(-x)); }

// -------- init: reset all cross-launch state (graph replays reuse globals) ----
__global__ void k_init() {
    int tid = blockIdx.x * blockDim.x + threadIdx.x;
    int n = 2 * BSZ * RR;
    for (int i = tid; i < n; i += gridDim.x * blockDim.x) ((float*)g_spk)[i] = 0.f;
    if (tid == 0) { g_bar_count = 0; g_bar_sense = 0; }
}

// -------- kernel A: currents[t][b][r] = dot(input[b][t][r][:], w_in) + b_in --
__global__ void k_currents(const float* __restrict__ inp,
                           const float* __restrict__ w_in,
                           const float* __restrict__ b_in) {
    __shared__ float sw[FF];
    int tid = threadIdx.x;
    if (tid < FF) sw[tid] = w_in[tid];
    __syncthreads();
    int lane = tid & 31, wid = tid >> 5;
    long long rid = (long long)blockIdx.x * 8 + wid;   // row over (b,t,r)
    if (rid >= (long long)BSZ * TT * RR) return;
    const float4* p = (const float4*)inp + rid * (FF / 4);
    float4 v = p[lane];
    float4 w = ((const float4*)sw)[lane];
    float s = v.x * w.x + v.y * w.y + v.z * w.z + v.w * w.w;
    #pragma unroll
    for (int o = 16; o; o >>= 1) s += __shfl_xor_sync(0xffffffffu, s, o);
    if (lane == 0) {
        int r = (int)(rid % RR);
        long long bt = rid / RR;
        int t = (int)(bt % TT);
        int b = (int)(bt / TT);
        g_currents[((long long)t * BSZ + b) * RR + r] = s + b_in[0];
    }
}

// -------- prep: compact (w_rnn*mask) rows into 256 (idx, w) pairs -----------
__global__ void k_prep(const float* __restrict__ w_rnn,
                       const float* __restrict__ mask) {
    int row = blockIdx.x * 8 + (threadIdx.x >> 5);
    int lane = threadIdx.x & 31;
    if (row >= NROWS) return;
    int base = 0;
    for (int c0 = 0; c0 < K2; c0 += 32) {
        float m = mask[(long long)row * K2 + c0 + lane];
        unsigned bal = __ballot_sync(0xffffffffu, m != 0.f);
        int pre = __popc(bal & ((1u << lane) - 1u));
        if (m != 0.f) {
            int pos = base + pre;
            if (pos < NNZ) {
                g_idx[row * NNZ + pos] = (unsigned short)(c0 + lane);
                g_wv [row * NNZ + pos] = w_rnn[(long long)row * K2 + c0 + lane];
            }
        }
        base += __popc(bal);
    }
}

// -------- kernel B: persistent recurrent scan -------------------------------
__global__ void __launch_bounds__(256, 1)
k_recurrent(const float* __restrict__ gating,
            const float* __restrict__ b_rnn,
            const float* __restrict__ tau_m,
            const float* __restrict__ tau_n,
            const float* __restrict__ w_ro,
            const float* __restrict__ b_ro,
            const float* __restrict__ tau_m_ro,
            float* __restrict__ out) {
    extern __shared__ char sm[];
    float*          s_w    = (float*)sm;                       // 64*256 f32
    unsigned short* s_idx  = (unsigned short*)(s_w + NG_ROWS * NNZ);   // 64*256 u16
    float*          s_kT   = (float*)(s_idx + NG_ROWS * NNZ);  // 1024*8 f32 (16B aligned)
    float*          s_proj = s_kT + K2 * NG_BAT;               // 8*64
    float*          s_d    = s_proj + NG_BAT * NG_ROWS;        // 8*16*4
    float*          s_mem  = s_d + NG_BAT * NG_NEUR * BR;      // 8*16
    float*          s_spk  = s_mem + NG_BAT * NG_NEUR;         // 8*16
    float*          s_beta = s_spk + NG_BAT * NG_NEUR;         // 64
    float*          s_alpha= s_beta + NG_ROWS;                 // 16
    float*          s_brnn = s_alpha + NG_NEUR;                // 64
    float*          s_memo = s_brnn + NG_ROWS;                 // 10
    float*          s_spko = s_memo + CC;                      // 10
    float*          s_ao   = s_spko + CC;                      // 10
    float*          s_bro  = s_ao + CC;                        // 10

    int tid = threadIdx.x, lane = tid & 31, wid = tid >> 5;
    int bid = blockIdx.x;
    int ng = bid >> 2;            // 0..31 neuron group (16 neurons)
    int bg = bid & 3;             // 0..3  batch group (8 batches)
    int row0 = ng * NG_ROWS;      // global branch-row base
    int b0 = bg * NG_BAT;

    // load resident weights/indices
    for (int i = tid; i < NG_ROWS * NNZ; i += 256) {
        s_w[i]   = g_wv [row0 * NNZ + i];
        s_idx[i] = g_idx[row0 * NNZ + i];
    }
    if (tid < NG_ROWS) {
        s_beta[tid] = sigmoidf_(tau_n[(ng * NG_NEUR + (tid >> 2)) * BR + (tid & 3)]);
        s_brnn[tid] = b_rnn[row0 + tid];
    }
    if (tid < NG_NEUR) s_alpha[tid] = sigmoidf_(tau_m[ng * NG_NEUR + tid]);
    for (int i = tid; i < NG_BAT * NG_NEUR * BR; i += 256) s_d[i] = 0.f;
    if (tid < NG_BAT * NG_NEUR) { s_mem[tid] = 0.f; s_spk[tid] = 0.f; }
    if (bid < BSZ && tid < CC) {
        s_memo[tid] = 0.f; s_spko[tid] = 0.f;
        s_ao[tid] = sigmoidf_(tau_m_ro[tid]); s_bro[tid] = b_ro[tid];
    }
    __syncthreads();

    for (int t = 0; t < TT; t++) {
        // ---- phase 1: fill kT = [currents(t) ; spk(prev)] transposed -------
        const float* cur = g_currents + (long long)t * BSZ * RR;
        const float* sp  = g_spk[t & 1];
        for (int e = tid; e < NG_BAT * RR; e += 256) {
            int bl = e >> 9, r = e & (RR - 1);
            s_kT[r * NG_BAT + bl]        = cur[(b0 + bl) * RR + r];
            s_kT[(RR + r) * NG_BAT + bl] = sp [(b0 + bl) * RR + r];
        }
        __syncthreads();

        // ---- phase 2: sparse GEMM, warp = one branch row at a time ---------
        #pragma unroll 1
        for (int rr = 0; rr < 8; rr++) {
            int row = wid * 8 + rr;
            const float*          wp = s_w   + row * NNZ;
            const unsigned short* ip = s_idx + row * NNZ;
            float a0=0,a1=0,a2=0,a3=0,a4=0,a5=0,a6=0,a7=0;
            #pragma unroll
            for (int c = 0; c < 8; c++) {
                int j = c * 32 + lane;
                float wv = wp[j];
                int id = ip[j];
                const float4* kp = (const float4*)(s_kT + id * NG_BAT);
                float4 q0 = kp[0], q1 = kp[1];
                a0 = fmaf(wv, q0.x, a0); a1 = fmaf(wv, q0.y, a1);
                a2 = fmaf(wv, q0.z, a2); a3 = fmaf(wv, q0.w, a3);
                a4 = fmaf(wv, q1.x, a4); a5 = fmaf(wv, q1.y, a5);
                a6 = fmaf(wv, q1.z, a6); a7 = fmaf(wv, q1.w, a7);
            }
            #pragma unroll
            for (int o = 16; o; o >>= 1) {
                a0 += __shfl_xor_sync(0xffffffffu, a0, o);
                a1 += __shfl_xor_sync(0xffffffffu, a1, o);
                a2 += __shfl_xor_sync(0xffffffffu, a2, o);
                a3 += __shfl_xor_sync(0xffffffffu, a3, o);
                a4 += __shfl_xor_sync(0xffffffffu, a4, o);
                a5 += __shfl_xor_sync(0xffffffffu, a5, o);
                a6 += __shfl_xor_sync(0xffffffffu, a6, o);
                a7 += __shfl_xor_sync(0xffffffffu, a7, o);
            }
            if (lane < 8) {
                float tot = lane==0?a0: lane==1?a1: lane==2?a2: lane==3?a3:
                            lane==4?a4: lane==5?a5: lane==6?a6: a7;
                s_proj[lane * NG_ROWS + row] = tot;
            }
        }
        __syncthreads();

        // ---- phase 3: dendrite + soma + gating + spike write ---------------
        if (tid < NG_BAT * NG_NEUR) {
            int bl = tid >> 4, nl = tid & 15;
            int b = b0 + bl, r = ng * NG_NEUR + nl;
            float g = gating[((long long)b * TT + t) * RR + r];
            float lin = 0.f;
            #pragma unroll
            for (int br = 0; br < BR; br++) {
                int row = nl * BR + br;
                float proj = s_proj[bl * NG_ROWS + row] + s_brnn[row];
                float beta = s_beta[row];
                float dold = s_d[(bl * NG_NEUR + nl) * BR + br];
                float dnew = beta * dold + (1.f - beta) * proj;
                lin += dnew;
                s_d[(bl * NG_NEUR + nl) * BR + br] = g * dnew + (1.f - g) * dold;
            }
            float alpha = s_alpha[nl];
            float mold = s_mem[bl * NG_NEUR + nl];
            float sold = s_spk[bl * NG_NEUR + nl];
            float mnew = mold * alpha + (1.f - alpha) * lin - VTH * sold;
            float snew = (mnew - VTH) > 0.f ? 1.f : 0.f;
            float mg = g * mnew + (1.f - g) * mold;
            float sg = g * snew + (1.f - g) * sold;
            s_mem[bl * NG_NEUR + nl] = mg;
            s_spk[bl * NG_NEUR + nl] = sg;
            g_spk[(t + 1) & 1][b * RR + r] = sg;
            out[OUT0 + ((long long)b * RR + r) * TT + t] = sg;
        }
        __syncthreads();

        // ---- global barrier (sense-reversing; one per step) ----------------
        if (tid == 0) {
            __threadfence();
            if (atomicAdd(&g_bar_count, 1u) == NCTA - 1) {
                atomicExch(&g_bar_count, 0u);
                __threadfence();
                atomicExch(&g_bar_sense, (unsigned)(t + 1));
            } else {
                while (*(volatile unsigned*)&g_bar_sense < (unsigned)(t + 1)) {
                    __nanosleep(32);
                }
            }
            __threadfence();
        }
        __syncthreads();

        // ---- readout LIF: CTA b (bid<32) handles batch b -------------------
        if (bid < BSZ) {
            const float* spn = g_spk[(t + 1) & 1] + bid * RR;
            for (int c = wid; c < CC; c += 8) {
                float s = 0.f;
                for (int i = lane; i < RR; i += 32)
                    s += spn[i] * __ldg(&w_ro[c * RR + i]);
                #pragma unroll
                for (int o = 16; o; o >>= 1) s += __shfl_xor_sync(0xffffffffu, s, o);
                if (lane == 0) {
                    float ro = s + s_bro[c];
                    float ao = s_ao[c];
                    float mo = s_memo[c] * ao + (1.f - ao) * ro - VTH * s_spko[c];
                    float so = (mo - VTH) > 0.f ? 1.f : 0.f;
                    s_memo[c] = mo; s_spko[c] = so;
                    out[((long long)bid * CC + c) * TT + t] = mo;
                }
            }
        }
        // no extra barrier needed: readout reads buffer not written until t+1's
        // phase 3, and this CTA's own phase 3 writes come after its next barrier.
    }
}

extern "C" void kernel_launch(void* const* d_in, const int* in_sizes, int n_in,
                              void* d_out, int out_size) {
    const float* inp      = (const float*)d_in[0];
    const float* gating   = (const float*)d_in[1];
    const float* w_in     = (const float*)d_in[2];
    const float* b_in     = (const float*)d_in[3];
    const float* w_rnn    = (const float*)d_in[4];
    const float* b_rnn    = (const float*)d_in[5];
    const float* tau_m    = (const float*)d_in[6];
    const float* tau_n    = (const float*)d_in[7];
    const float* w_ro     = (const float*)d_in[8];
    const float* b_ro     = (const float*)d_in[9];
    const float* tau_m_ro = (const float*)d_in[10];
    const float* mask     = (const float*)d_in[11];
    float* out = (float*)d_out;

    // dynamic smem for recurrent kernel
    // 65536(w) + 32768(idx) + 32768(kT) + 2048(proj) + 2048(d) + 512 + 512
    // + 256(beta) + 64(alpha) + 256(brnn) + 4*40(readout) = 136928 -> pad
    static int smem_set = 0;
    int smem_bytes = 137216;
    if (!smem_set) {
        cudaFuncSetAttribute(k_recurrent,
                             cudaFuncAttributeMaxDynamicSharedMemorySize,
                             smem_bytes);
        smem_set = 1;
    }

    k_init<<<64, 256>>>();

    long long total_rows = (long long)BSZ * TT * RR;   // 3,276,800
    int gridA = (int)((total_rows + 7) / 8);
    k_currents<<<gridA, 256>>>(inp, w_in, b_in);

    k_prep<<<NROWS / 8, 256>>>(w_rnn, mask);

    k_recurrent<<<NCTA, 256, smem_bytes>>>(gating, b_rnn, tau_m, tau_n,
                                           w_ro, b_ro, tau_m_ro, out);
}

// round 4
// speedup vs baseline: 1.1220x; 1.1170x over previous
#include <cuda_runtime.h>
#include <cuda_bf16.h>

// Problem constants
#define BSZ 32
#define TT  200
#define RR  512
#define FF  128
#define BR  4
#define CC  10
#define K2  1024          // 2*R
#define NNZ 256           // nonzeros per branch row
#define NROWS 2048        // R*BR
#define VTH 0.5f

#define NCTA_TOTAL 148    // all co-resident (1 CTA/SM)
#define GEMM_CTAS  128    // each: 16 branch rows (4 neurons) x 32 batches
#define RO_CTAS    (NCTA_TOTAL - GEMM_CTAS)   // 20 readout CTAs

#define KT_STRIDE 33      // padded row stride (floats) -> conflict-free
#define KT_STRIDE_B (KT_STRIDE*4)

#define OUT0 (BSZ*CC*TT)  // offset of spikes block in d_out

// -------- scratch (device globals) --------
__device__ float    g_currents[TT * BSZ * RR];   // [T][B][R]
__device__ float    g_spk[2][BSZ * RR];          // ping-pong spikes [B][R]
__device__ unsigned g_pidx[NROWS * NNZ];         // idx * KT_STRIDE_B (bytes)
__device__ float    g_wv [NROWS * NNZ];          // compacted masked weights
__device__ unsigned g_bar_count;
__device__ unsigned g_bar_sense;

__device__ __forceinline__ float sigmoidf_(float x) { return 1.f / (1.f + __expf(-x)); }

// -------- init ----------
__global__ void k_init() {
    int tid = blockIdx.x * blockDim.x + threadIdx.x;
    int n = 2 * BSZ * RR;
    for (int i = tid; i < n; i += gridDim.x * blockDim.x) ((float*)g_spk)[i] = 0.f;
    if (tid == 0) { g_bar_count = 0; g_bar_sense = 0; }
}

// -------- kernel A: currents[t][b][r] = dot(input[b][t][r][:], w_in)+b_in ----
__global__ void k_currents(const float* __restrict__ inp,
                           const float* __restrict__ w_in,
                           const float* __restrict__ b_in) {
    __shared__ float sw[FF];
    int tid = threadIdx.x;
    if (tid < FF) sw[tid] = w_in[tid];
    __syncthreads();
    int lane = tid & 31, wid = tid >> 5;
    long long rid = (long long)blockIdx.x * 8 + wid;   // row over (b,t,r)
    if (rid >= (long long)BSZ * TT * RR) return;
    const float4* p = (const float4*)inp + rid * (FF / 4);
    float4 v = p[lane];
    float4 w = ((const float4*)sw)[lane];
    float s = v.x * w.x + v.y * w.y + v.z * w.z + v.w * w.w;
    #pragma unroll
    for (int o = 16; o; o >>= 1) s += __shfl_xor_sync(0xffffffffu, s, o);
    if (lane == 0) {
        int r = (int)(rid % RR);
        long long bt = rid / RR;
        int t = (int)(bt % TT);
        int b = (int)(bt / TT);
        g_currents[((long long)t * BSZ + b) * RR + r] = s + b_in[0];
    }
}

// -------- prep: compact (w_rnn*mask) rows into 256 (pidx, w) pairs ----------
__global__ void k_prep(const float* __restrict__ w_rnn,
                       const float* __restrict__ mask) {
    int row = blockIdx.x * 8 + (threadIdx.x >> 5);
    int lane = threadIdx.x & 31;
    if (row >= NROWS) return;
    int base = 0;
    for (int c0 = 0; c0 < K2; c0 += 32) {
        float m = mask[(long long)row * K2 + c0 + lane];
        unsigned bal = __ballot_sync(0xffffffffu, m != 0.f);
        int pre = __popc(bal & ((1u << lane) - 1u));
        if (m != 0.f) {
            int pos = base + pre;
            if (pos < NNZ) {
                g_pidx[row * NNZ + pos] = (unsigned)(c0 + lane) * KT_STRIDE_B;
                g_wv [row * NNZ + pos] = w_rnn[(long long)row * K2 + c0 + lane];
            }
        }
        base += __popc(bal);
    }
}

// global sense-reversing barrier (all NCTA_TOTAL CTAs, one per step)
__device__ __forceinline__ void step_barrier(int tid, unsigned target) {
    __syncthreads();
    if (tid == 0) {
        __threadfence();
        if (atomicAdd(&g_bar_count, 1u) == NCTA_TOTAL - 1) {
            atomicExch(&g_bar_count, 0u);
            __threadfence();
            atomicExch(&g_bar_sense, target);
        } else {
            while (*(volatile unsigned*)&g_bar_sense < target) __nanosleep(64);
        }
        __threadfence();
    }
    __syncthreads();
}

// -------- kernel B: persistent recurrent scan -------------------------------
__global__ void __launch_bounds__(256, 1)
k_recurrent(const float* __restrict__ gating,
            const float* __restrict__ b_rnn,
            const float* __restrict__ tau_m,
            const float* __restrict__ tau_n,
            const float* __restrict__ w_ro,
            const float* __restrict__ b_ro,
            const float* __restrict__ tau_m_ro,
            float* __restrict__ out) {
    extern __shared__ char sm[];
    // layout (16B-aligned chunks)
    float*    s_w    = (float*)sm;                               // 16*256 f32  (16KB)
    unsigned* s_pidx = (unsigned*)(s_w + 16 * NNZ);              // 16*256 u32  (16KB)
    float*    s_kT   = (float*)(s_pidx + 16 * NNZ);              // 1024*33 f32 (132KB)
    float*    s_proj = s_kT + K2 * KT_STRIDE;                    // 16*32
    float*    s_d    = s_proj + 16 * 32;                         // 128*4
    float*    s_mem  = s_d + 128 * 4;                            // 128
    float*    s_spk  = s_mem + 128;                              // 128
    float*    s_beta = s_spk + 128;                              // 16
    float*    s_brnn = s_beta + 16;                              // 16
    float*    s_alphaN = s_brnn + 16;                            // 4 (+pad)

    int tid = threadIdx.x, lane = tid & 31, wid = tid >> 5;
    int bid = blockIdx.x;

    if (bid >= GEMM_CTAS) {
        // ================= readout CTAs =================
        float* s_wro = (float*)sm;                   // 10*512 f32 = 20KB
        for (int i = tid; i < CC * RR; i += 256) s_wro[i] = w_ro[i];
        __syncthreads();

        int gwarp = (bid - GEMM_CTAS) * 8 + wid;     // 0..159
        int t0 = gwarp * 2, t1 = t0 + 1;             // tasks (b*10+c), < 320
        int b_0 = t0 / CC, c_0 = t0 % CC;
        int b_1 = t1 / CC, c_1 = t1 % CC;
        float ao0 = sigmoidf_(tau_m_ro[c_0]), bro0 = b_ro[c_0];
        float ao1 = sigmoidf_(tau_m_ro[c_1]), bro1 = b_ro[c_1];
        float m0 = 0.f, sp0 = 0.f, m1 = 0.f, sp1 = 0.f;

        for (int t = 0; t < TT; t++) {
            step_barrier(tid, (unsigned)(t + 1));
            const float* spn = g_spk[(t + 1) & 1];
            float sum0 = 0.f, sum1 = 0.f;
            const float* sb0 = spn + b_0 * RR;
            const float* sb1 = spn + b_1 * RR;
            #pragma unroll
            for (int i = 0; i < RR; i += 32) {
                sum0 += sb0[i + lane] * s_wro[c_0 * RR + i + lane];
                sum1 += sb1[i + lane] * s_wro[c_1 * RR + i + lane];
            }
            #pragma unroll
            for (int o = 16; o; o >>= 1) {
                sum0 += __shfl_xor_sync(0xffffffffu, sum0, o);
                sum1 += __shfl_xor_sync(0xffffffffu, sum1, o);
            }
            float ro0 = sum0 + bro0;
            m0 = m0 * ao0 + (1.f - ao0) * ro0 - VTH * sp0;
            sp0 = (m0 - VTH) > 0.f ? 1.f : 0.f;
            float ro1 = sum1 + bro1;
            m1 = m1 * ao1 + (1.f - ao1) * ro1 - VTH * sp1;
            sp1 = (m1 - VTH) > 0.f ? 1.f : 0.f;
            if (lane == 0) {
                out[(long long)t0 * TT + t] = m0;   // (b*CC+c)*TT + t
                out[(long long)t1 * TT + t] = m1;
            }
        }
        return;
    }

    // ================= GEMM CTAs =================
    int row0 = bid * 16;          // global branch-row base (16 rows = 4 neurons)
    int n0 = bid * 4;             // global neuron base

    for (int i = tid; i < 16 * NNZ; i += 256) {
        s_w[i]    = g_wv  [row0 * NNZ + i];
        s_pidx[i] = g_pidx[row0 * NNZ + i];
    }
    if (tid < 16) {
        s_beta[tid] = sigmoidf_(tau_n[(n0 + (tid >> 2)) * BR + (tid & 3)]);
        s_brnn[tid] = b_rnn[row0 + tid];
    }
    if (tid < 4) s_alphaN[tid] = sigmoidf_(tau_m[n0 + tid]);
    if (tid < 128) {
        s_mem[tid] = 0.f; s_spk[tid] = 0.f;
        #pragma unroll
        for (int br = 0; br < BR; br++) s_d[tid * 4 + br] = 0.f;
    }
    __syncthreads();

    const char* ktb = (const char*)s_kT + lane * 4;   // lane = batch column

    for (int t = 0; t < TT; t++) {
        // ---- fill kT[k][b] (padded stride 33): currents then spikes --------
        {
            const float* cur = g_currents + (long long)t * BSZ * RR;
            const float* sp  = g_spk[t & 1];
            #pragma unroll 4
            for (int e = tid; e < BSZ * RR; e += 256) {
                int b = e >> 9, r = e & (RR - 1);
                s_kT[r * KT_STRIDE + b]        = cur[e];
                s_kT[(RR + r) * KT_STRIDE + b] = sp[e];
            }
        }
        __syncthreads();

        // ---- sparse GEMM: warp = 2 rows, lane = batch ----------------------
        {
            int r0 = wid * 2, r1 = r0 + 1;
            const float*    wp0 = s_w    + r0 * NNZ;
            const unsigned* pp0 = s_pidx + r0 * NNZ;
            const float*    wp1 = s_w    + r1 * NNZ;
            const unsigned* pp1 = s_pidx + r1 * NNZ;
            float a0 = 0.f, a1 = 0.f, c0 = 0.f, c1 = 0.f;
            #pragma unroll 4
            for (int j = 0; j < NNZ; j += 4) {
                float4   w0 = *(const float4*)(wp0 + j);
                uint4    q0 = *(const uint4*)(pp0 + j);
                float4   w1 = *(const float4*)(wp1 + j);
                uint4    q1 = *(const uint4*)(pp1 + j);
                a0 = fmaf(w0.x, *(const float*)(ktb + q0.x), a0);
                a1 = fmaf(w0.y, *(const float*)(ktb + q0.y), a1);
                a0 = fmaf(w0.z, *(const float*)(ktb + q0.z), a0);
                a1 = fmaf(w0.w, *(const float*)(ktb + q0.w), a1);
                c0 = fmaf(w1.x, *(const float*)(ktb + q1.x), c0);
                c1 = fmaf(w1.y, *(const float*)(ktb + q1.y), c1);
                c0 = fmaf(w1.z, *(const float*)(ktb + q1.z), c0);
                c1 = fmaf(w1.w, *(const float*)(ktb + q1.w), c1);
            }
            s_proj[r0 * 32 + lane] = a0 + a1;
            s_proj[r1 * 32 + lane] = c0 + c1;
        }
        __syncthreads();

        // ---- dendrite + soma + gating + spike write ------------------------
        if (tid < 128) {
            int b = tid >> 2, nl = tid & 3;
            int r = n0 + nl;
            float g = gating[((long long)b * TT + t) * RR + r];
            float lin = 0.f;
            #pragma unroll
            for (int br = 0; br < BR; br++) {
                int row = nl * 4 + br;
                float proj = s_proj[row * 32 + b] + s_brnn[row];
                float beta = s_beta[row];
                float dold = s_d[tid * 4 + br];
                float dnew = beta * dold + (1.f - beta) * proj;
                lin += dnew;
                s_d[tid * 4 + br] = g * dnew + (1.f - g) * dold;
            }
            float alpha = s_alphaN[nl];
            float mold = s_mem[tid];
            float sold = s_spk[tid];
            float mnew = mold * alpha + (1.f - alpha) * lin - VTH * sold;
            float snew = (mnew - VTH) > 0.f ? 1.f : 0.f;
            float mg = g * mnew + (1.f - g) * mold;
            float sg = g * snew + (1.f - g) * sold;
            s_mem[tid] = mg;
            s_spk[tid] = sg;
            g_spk[(t + 1) & 1][b * RR + r] = sg;
            out[OUT0 + ((long long)b * RR + r) * TT + t] = sg;
        }

        // ---- global barrier ------------------------------------------------
        step_barrier(tid, (unsigned)(t + 1));
    }
}

extern "C" void kernel_launch(void* const* d_in, const int* in_sizes, int n_in,
                              void* d_out, int out_size) {
    const float* inp      = (const float*)d_in[0];
    const float* gating   = (const float*)d_in[1];
    const float* w_in     = (const float*)d_in[2];
    const float* b_in     = (const float*)d_in[3];
    const float* w_rnn    = (const float*)d_in[4];
    const float* b_rnn    = (const float*)d_in[5];
    const float* tau_m    = (const float*)d_in[6];
    const float* tau_n    = (const float*)d_in[7];
    const float* w_ro     = (const float*)d_in[8];
    const float* b_ro     = (const float*)d_in[9];
    const float* tau_m_ro = (const float*)d_in[10];
    const float* mask     = (const float*)d_in[11];
    float* out = (float*)d_out;

    // smem: 16KB(w) + 16KB(pidx) + 135168(kT) + 2048(proj) + 2048(d)
    //       + 512 + 512 + small  ~= 173.3 KB
    int smem_bytes = 174080;
    cudaFuncSetAttribute(k_recurrent,
                         cudaFuncAttributeMaxDynamicSharedMemorySize,
                         smem_bytes);

    k_init<<<64, 256>>>();

    long long total_rows = (long long)BSZ * TT * RR;   // 3,276,800
    int gridA = (int)((total_rows + 7) / 8);
    k_currents<<<gridA, 256>>>(inp, w_in, b_in);

    k_prep<<<NROWS / 8, 256>>>(w_rnn, mask);

    k_recurrent<<<NCTA_TOTAL, 256, smem_bytes>>>(gating, b_rnn, tau_m, tau_n,
                                                 w_ro, b_ro, tau_m_ro, out);
}

// round 5
// speedup vs baseline: 1.5807x; 1.4088x over previous
#include <cuda_runtime.h>
#include <cuda_bf16.h>

// Problem constants
#define BSZ 32
#define TT  200
#define RR  512
#define FF  128
#define BR  4
#define CC  10
#define K2  1024          // 2*R
#define NNZ 256           // nonzeros per branch row
#define NROWS 2048        // R*BR
#define VTH 0.5f

#define NCTA_TOTAL 148    // all co-resident (1 CTA/SM)
#define GEMM_CTAS  128    // each: 16 branch rows (4 neurons) x 32 batches
#define NTHREADS   512

#define KT_STRIDE 36      // padded row stride (floats): float4-aligned, conflict-free
#define KT_STRIDE_B (KT_STRIDE*4)

#define OUT0 (BSZ*CC*TT)  // offset of spikes block in d_out

// -------- scratch (device globals) --------
__device__ float    g_currents[TT * RR * BSZ];   // [T][R][B]  (batch-minor!)
__device__ float    g_spk[2][RR * BSZ];          // ping-pong spikes [R][B]
__device__ unsigned g_pidx[NROWS * NNZ];         // idx * KT_STRIDE_B (bytes)
__device__ float    g_wv [NROWS * NNZ];          // compacted masked weights
__device__ volatile unsigned g_arrive[160];      // per-CTA arrival flags
__device__ volatile unsigned g_sense;            // broadcast release word

__device__ __forceinline__ float sigmoidf_(float x) { return 1.f / (1.f + __expf(-x)); }

// -------- init: reset cross-launch state (graph replays reuse globals) ------
__global__ void k_init() {
    int tid = blockIdx.x * blockDim.x + threadIdx.x;
    int n = 2 * RR * BSZ;
    for (int i = tid; i < n; i += gridDim.x * blockDim.x) ((float*)g_spk)[i] = 0.f;
    if (tid < 160) g_arrive[tid] = 0;
    if (tid == 0) g_sense = 0;
}

// -------- kernel A: currents[t][r][b] = dot(input[b][t][r][:], w_in)+b_in ---
__global__ void k_currents(const float* __restrict__ inp,
                           const float* __restrict__ w_in,
                           const float* __restrict__ b_in) {
    __shared__ float sw[FF];
    int tid = threadIdx.x;
    if (tid < FF) sw[tid] = w_in[tid];
    __syncthreads();
    int lane = tid & 31, wid = tid >> 5;
    long long rid = (long long)blockIdx.x * 8 + wid;   // row over (b,t,r)
    if (rid >= (long long)BSZ * TT * RR) return;
    const float4* p = (const float4*)inp + rid * (FF / 4);
    float4 v = p[lane];
    float4 w = ((const float4*)sw)[lane];
    float s = v.x * w.x + v.y * w.y + v.z * w.z + v.w * w.w;
    #pragma unroll
    for (int o = 16; o; o >>= 1) s += __shfl_xor_sync(0xffffffffu, s, o);
    if (lane == 0) {
        int r = (int)(rid % RR);
        long long bt = rid / RR;
        int t = (int)(bt % TT);
        int b = (int)(bt / TT);
        g_currents[((long long)t * RR + r) * BSZ + b] = s + b_in[0];
    }
}

// -------- prep: compact (w_rnn*mask) rows into 256 (pidx, w) pairs ----------
__global__ void k_prep(const float* __restrict__ w_rnn,
                       const float* __restrict__ mask) {
    int row = blockIdx.x * 8 + (threadIdx.x >> 5);
    int lane = threadIdx.x & 31;
    if (row >= NROWS) return;
    int base = 0;
    for (int c0 = 0; c0 < K2; c0 += 32) {
        float m = mask[(long long)row * K2 + c0 + lane];
        unsigned bal = __ballot_sync(0xffffffffu, m != 0.f);
        int pre = __popc(bal & ((1u << lane) - 1u));
        if (m != 0.f) {
            int pos = base + pre;
            if (pos < NNZ) {
                g_pidx[row * NNZ + pos] = (unsigned)(c0 + lane) * KT_STRIDE_B;
                g_wv [row * NNZ + pos] = w_rnn[(long long)row * K2 + c0 + lane];
            }
        }
        base += __popc(bal);
    }
}

// global barrier: per-CTA flag arrival + CTA0 aggregates + sense broadcast
__device__ __forceinline__ void step_barrier(int tid, int bid, unsigned target) {
    __syncthreads();
    if (bid == 0) {
        if (tid < 32) {
            if (tid == 0) { __threadfence(); g_arrive[0] = target; }
            bool done = false;
            while (!done) {
                bool ok = true;
                #pragma unroll
                for (int k = 0; k < 5; k++) {
                    int i = tid + k * 32;
                    unsigned v = (i < NCTA_TOTAL) ? g_arrive[i] : target;
                    if (v < target) ok = false;
                }
                done = __all_sync(0xffffffffu, ok);
                if (!done) __nanosleep(40);
            }
            if (tid == 0) { __threadfence(); g_sense = target; }
        }
        __syncthreads();
        __threadfence();
    } else {
        if (tid == 0) {
            __threadfence();
            g_arrive[bid] = target;
            while (g_sense < target) __nanosleep(40);
            __threadfence();
        }
        __syncthreads();
    }
}

// -------- kernel B: persistent recurrent scan -------------------------------
__global__ void __launch_bounds__(NTHREADS, 1)
k_recurrent(const float* __restrict__ gating,
            const float* __restrict__ b_rnn,
            const float* __restrict__ tau_m,
            const float* __restrict__ tau_n,
            const float* __restrict__ w_ro,
            const float* __restrict__ b_ro,
            const float* __restrict__ tau_m_ro,
            float* __restrict__ out) {
    extern __shared__ char sm[];

    int tid = threadIdx.x, lane = tid & 31, wid = tid >> 5;
    int bid = blockIdx.x;

    if (bid >= GEMM_CTAS) {
        // ================= readout CTAs (20) =================
        // smem: w_ro [10*512] + spike stage [512*33]
        float* s_wro = (float*)sm;                        // 20KB
        float* s_sp  = s_wro + CC * RR;                   // 512*33 f32 ~67.6KB
        for (int i = tid; i < CC * RR; i += NTHREADS) s_wro[i] = w_ro[i];
        __syncthreads();

        int task = (bid - GEMM_CTAS) * 16 + wid;          // 0..319 = b*CC+c
        int b_ = task / CC, c_ = task % CC;
        float ao = sigmoidf_(tau_m_ro[c_]), bro = b_ro[c_];
        float m0 = 0.f, sp0 = 0.f;

        for (int t = 0; t < TT; t++) {
            step_barrier(tid, bid, (unsigned)(t + 1));
            // stage spikes [r][b] -> smem padded [r*33+b]
            const float* spn = g_spk[(t + 1) & 1];
            for (int e = tid; e < RR * BSZ; e += NTHREADS) {
                int r = e >> 5, b = e & 31;
                s_sp[r * 33 + b] = spn[e];
            }
            __syncthreads();
            float sum = 0.f;
            #pragma unroll
            for (int i = 0; i < RR; i += 32)
                sum += s_sp[(i + lane) * 33 + b_] * s_wro[c_ * RR + i + lane];
            #pragma unroll
            for (int o = 16; o; o >>= 1) sum += __shfl_xor_sync(0xffffffffu, sum, o);
            m0 = m0 * ao + (1.f - ao) * (sum + bro) - VTH * sp0;
            sp0 = (m0 - VTH) > 0.f ? 1.f : 0.f;
            if (lane == 0) out[(long long)task * TT + t] = m0;
            __syncthreads();   // protect s_sp before next stage fill
        }
        return;
    }

    // ================= GEMM CTAs (128) =================
    float*    s_w    = (float*)sm;                               // 16*256 f32 (16KB)
    unsigned* s_pidx = (unsigned*)(s_w + 16 * NNZ);              // 16*256 u32 (16KB)
    float*    s_kT   = (float*)(s_pidx + 16 * NNZ);              // 1024*36 f32 (144KB)
    float*    s_proj = s_kT + K2 * KT_STRIDE;                    // 16*32
    float*    s_d    = s_proj + 16 * 32;                         // 128*4
    float*    s_mem  = s_d + 128 * 4;                            // 128
    float*    s_spk  = s_mem + 128;                              // 128
    float*    s_beta = s_spk + 128;                              // 16
    float*    s_brnn = s_beta + 16;                              // 16
    float*    s_alphaN = s_brnn + 16;                            // 4

    int row0 = bid * 16;          // global branch-row base (16 rows = 4 neurons)
    int n0 = bid * 4;             // global neuron base

    for (int i = tid; i < 16 * NNZ; i += NTHREADS) {
        s_w[i]    = g_wv  [row0 * NNZ + i];
        s_pidx[i] = g_pidx[row0 * NNZ + i];
    }
    if (tid < 16) {
        s_beta[tid] = sigmoidf_(tau_n[(n0 + (tid >> 2)) * BR + (tid & 3)]);
        s_brnn[tid] = b_rnn[row0 + tid];
    }
    if (tid < 4) s_alphaN[tid] = sigmoidf_(tau_m[n0 + tid]);
    if (tid < 128) {
        s_mem[tid] = 0.f; s_spk[tid] = 0.f;
        #pragma unroll
        for (int br = 0; br < BR; br++) s_d[tid * 4 + br] = 0.f;
    }
    __syncthreads();

    const char* ktb = (const char*)s_kT + lane * 4;   // lane = batch column

    for (int t = 0; t < TT; t++) {
        // ---- fill kT[k][b]: coalesced LDG.128 -> aligned STS.128 -----------
        {
            const float4* cur = (const float4*)(g_currents + (long long)t * RR * BSZ);
            const float4* sp  = (const float4*)(g_spk[t & 1]);
            #pragma unroll
            for (int i = tid; i < RR * BSZ / 4; i += NTHREADS) {
                int r = i >> 3, b4 = i & 7;          // 8 float4 per row
                *(float4*)(s_kT + r * KT_STRIDE + b4 * 4)          = cur[i];
                *(float4*)(s_kT + (RR + r) * KT_STRIDE + b4 * 4)   = sp[i];
            }
        }
        __syncthreads();

        // ---- sparse GEMM: warp = 1 row, lane = batch -----------------------
        {
            const float*    wp = s_w    + wid * NNZ;
            const unsigned* pp = s_pidx + wid * NNZ;
            float a0 = 0.f, a1 = 0.f, a2 = 0.f, a3 = 0.f;
            #pragma unroll 4
            for (int j = 0; j < NNZ; j += 4) {
                float4 w4 = *(const float4*)(wp + j);
                uint4  q4 = *(const uint4*)(pp + j);
                a0 = fmaf(w4.x, *(const float*)(ktb + q4.x), a0);
                a1 = fmaf(w4.y, *(const float*)(ktb + q4.y), a1);
                a2 = fmaf(w4.z, *(const float*)(ktb + q4.z), a2);
                a3 = fmaf(w4.w, *(const float*)(ktb + q4.w), a3);
            }
            s_proj[wid * 32 + lane] = (a0 + a1) + (a2 + a3);
        }
        __syncthreads();

        // ---- dendrite + soma + gating + spike write ------------------------
        if (tid < 128) {
            int b = tid >> 2, nl = tid & 3;
            int r = n0 + nl;
            float g = gating[((long long)b * TT + t) * RR + r];
            float lin = 0.f;
            #pragma unroll
            for (int br = 0; br < BR; br++) {
                int row = nl * 4 + br;
                float proj = s_proj[row * 32 + b] + s_brnn[row];
                float beta = s_beta[row];
                float dold = s_d[tid * 4 + br];
                float dnew = beta * dold + (1.f - beta) * proj;
                lin += dnew;
                s_d[tid * 4 + br] = g * dnew + (1.f - g) * dold;
            }
            float alpha = s_alphaN[nl];
            float mold = s_mem[tid];
            float sold = s_spk[tid];
            float mnew = mold * alpha + (1.f - alpha) * lin - VTH * sold;
            float snew = (mnew - VTH) > 0.f ? 1.f : 0.f;
            float mg = g * mnew + (1.f - g) * mold;
            float sg = g * snew + (1.f - g) * sold;
            s_mem[tid] = mg;
            s_spk[tid] = sg;
            g_spk[(t + 1) & 1][r * BSZ + b] = sg;
            out[OUT0 + ((long long)b * RR + r) * TT + t] = sg;
        }

        // ---- global barrier ------------------------------------------------
        step_barrier(tid, bid, (unsigned)(t + 1));
    }
}

extern "C" void kernel_launch(void* const* d_in, const int* in_sizes, int n_in,
                              void* d_out, int out_size) {
    const float* inp      = (const float*)d_in[0];
    const float* gating   = (const float*)d_in[1];
    const float* w_in     = (const float*)d_in[2];
    const float* b_in     = (const float*)d_in[3];
    const float* w_rnn    = (const float*)d_in[4];
    const float* b_rnn    = (const float*)d_in[5];
    const float* tau_m    = (const float*)d_in[6];
    const float* tau_n    = (const float*)d_in[7];
    const float* w_ro     = (const float*)d_in[8];
    const float* b_ro     = (const float*)d_in[9];
    const float* tau_m_ro = (const float*)d_in[10];
    const float* mask     = (const float*)d_in[11];
    float* out = (float*)d_out;

    // GEMM CTA smem: 16KB(w)+16KB(pidx)+147456(kT)+2048(proj)+2048(d)
    //                +512+512+~200  ~= 185.3 KB  (readout CTAs use ~88KB)
    int smem_bytes = 186368;
    cudaFuncSetAttribute(k_recurrent,
                         cudaFuncAttributeMaxDynamicSharedMemorySize,
                         smem_bytes);

    k_init<<<64, 256>>>();

    long long total_rows = (long long)BSZ * TT * RR;   // 3,276,800
    int gridA = (int)((total_rows + 7) / 8);
    k_currents<<<gridA, 256>>>(inp, w_in, b_in);

    k_prep<<<NROWS / 8, 256>>>(w_rnn, mask);

    k_recurrent<<<NCTA_TOTAL, NTHREADS, smem_bytes>>>(gating, b_rnn, tau_m, tau_n,
                                                      w_ro, b_ro, tau_m_ro, out);
}